// round 6
// baseline (speedup 1.0000x reference)
#include <cuda_runtime.h>
#include <cstdint>

#define NROW 8192
#define KDIM 8192
#define DIN  256
#define DOUT 256

// ---------------- scratch (static device globals; no allocations) ----------
__device__ float g_dinv[NROW];          // 32 KB
__device__ float g_Y[NROW * DIN];       // 8 MB  (d_j^-1/2 * X, rounded to tf32)
__device__ float g_H[NROW * DIN];       // 8 MB  (A_norm @ X, fp32)

// ---------------- helpers ---------------------------------------------------
__device__ __forceinline__ uint32_t f2tf32(float x) {
    uint32_t r;
    asm("cvt.rna.tf32.f32 %0, %1;" : "=r"(r) : "f"(x));
    return r;
}

__device__ __forceinline__ void cp_async16(void* smem, const void* gmem) {
    uint32_t s = (uint32_t)__cvta_generic_to_shared(smem);
    asm volatile("cp.async.cg.shared.global [%0], [%1], 16;\n" :: "r"(s), "l"(gmem));
}
__device__ __forceinline__ void cp_commit() {
    asm volatile("cp.async.commit_group;\n" ::);
}
__device__ __forceinline__ void cp_wait0() {
    asm volatile("cp.async.wait_group 0;\n" ::);
}

__device__ __forceinline__ void mma_tf32(float (&c)[4], const uint32_t (&a)[4],
                                         uint32_t b0, uint32_t b1) {
    asm volatile(
        "mma.sync.aligned.m16n8k8.row.col.f32.tf32.tf32.f32 "
        "{%0,%1,%2,%3}, {%4,%5,%6,%7}, {%8,%9}, {%0,%1,%2,%3};\n"
        : "+f"(c[0]), "+f"(c[1]), "+f"(c[2]), "+f"(c[3])
        : "r"(a[0]), "r"(a[1]), "r"(a[2]), "r"(a[3]), "r"(b0), "r"(b1));
}

// ---------------- kernel 1: d_inv_sqrt = rsqrt(rowsum(A)) -------------------
__global__ __launch_bounds__(256) void rowsum_kernel(const float* __restrict__ A) {
    int row = blockIdx.x;
    const float4* a4 = reinterpret_cast<const float4*>(A + (size_t)row * KDIM);
    int t = threadIdx.x;
    float s = 0.0f;
#pragma unroll
    for (int j = 0; j < 8; j++) {
        float4 v = a4[t + 256 * j];
        s += (v.x + v.y) + (v.z + v.w);
    }
    __shared__ float red[256];
    red[t] = s;
    __syncthreads();
#pragma unroll
    for (int off = 128; off > 0; off >>= 1) {
        if (t < off) red[t] += red[t + off];
        __syncthreads();
    }
    if (t == 0) g_dinv[row] = rsqrtf(red[0]);
}

// ---------------- kernel 2: Y[j,:] = tf32_rn(d_j^-1/2 * X[j,:]) -------------
__global__ __launch_bounds__(256) void prepY_kernel(const float* __restrict__ X) {
    int idx = blockIdx.x * 256 + threadIdx.x;      // float4 index, 524288 total
    float4 v = reinterpret_cast<const float4*>(X)[idx];
    int row = idx >> 6;                            // 64 float4 per row of 256
    float d = g_dinv[row];
    uint4 o;
    o.x = f2tf32(v.x * d);
    o.y = f2tf32(v.y * d);
    o.z = f2tf32(v.z * d);
    o.w = f2tf32(v.w * d);
    reinterpret_cast<uint4*>(g_Y)[idx] = o;
}

// ---------------- kernel 3: H = diag(d) * (A @ Y)  (tf32 mma) ---------------
// CTA tile: 64 (M) x 256 (N, full), K-tile 16. 128 CTAs. 8 warps = 2x4 grid,
// warp tile 32x64 -> 2 m-frags x 8 n-frags of m16n8k8.
#define BM 64
#define BK 16
#define SA 20    // As row stride (floats): 80 B, 16B-aligned, conflict-free frags
#define SY 260   // Ys row stride (floats): 1040 B, 16B-aligned, <=2-way frags
#define NK (KDIM / BK)

__global__ __launch_bounds__(256) void gemm1_kernel(const float* __restrict__ A) {
    __shared__ float As[2][BM * SA];     // 2 * 5120 floats = 40 KB? no: 10 KB
    __shared__ float Ys[2][BK * SY];     // 2 * 4160 floats = 33.3 KB

    int t = threadIdx.x;
    int wid = t >> 5, lane = t & 31;
    int warp_m = wid >> 2, warp_n = wid & 3;
    int ctaM = blockIdx.x * BM;

    float acc[2][8][4];
#pragma unroll
    for (int mi = 0; mi < 2; mi++)
#pragma unroll
        for (int ni = 0; ni < 8; ni++)
#pragma unroll
            for (int q = 0; q < 4; q++) acc[mi][ni][q] = 0.0f;

    // A staging: thread -> 1 float4. row = t/4, col (floats) = (t%4)*4
    int ar = t >> 2;
    int ac = (t & 3) * 4;
    const float* Aptr = A + (size_t)(ctaM + ar) * KDIM + ac;

    // ---- prologue: stage tile 0 ----
    float4 aReg = *reinterpret_cast<const float4*>(Aptr);
#pragma unroll
    for (int j = 0; j < 4; j++) {
        int v = j * 256 + t;
        int yr = v >> 6;                 // 0..15
        int yc = (v & 63) * 4;           // 0..252
        cp_async16(&Ys[0][yr * SY + yc], g_Y + (size_t)yr * DIN + yc);
    }
    cp_commit();
    {
        uint4 o = make_uint4(f2tf32(aReg.x), f2tf32(aReg.y), f2tf32(aReg.z), f2tf32(aReg.w));
        *reinterpret_cast<uint4*>(&As[0][ar * SA + ac]) = o;
    }
    cp_wait0();
    __syncthreads();

    int buf = 0;
    for (int kt = 0; kt < NK; ++kt) {
        int nbuf = buf ^ 1;
        bool hasNext = (kt + 1 < NK);
        float4 aN;
        if (hasNext) {
            aN = *reinterpret_cast<const float4*>(Aptr + (size_t)(kt + 1) * BK);
            int k0 = (kt + 1) * BK;
#pragma unroll
            for (int j = 0; j < 4; j++) {
                int v = j * 256 + t;
                int yr = v >> 6;
                int yc = (v & 63) * 4;
                cp_async16(&Ys[nbuf][yr * SY + yc], g_Y + (size_t)(k0 + yr) * DIN + yc);
            }
            cp_commit();
        }

        // ---- compute on buf: 2 k8-steps, 16 mma each ----
#pragma unroll
        for (int k8 = 0; k8 < 2; k8++) {
            int kc = k8 * 8;
            uint32_t af[2][4];
#pragma unroll
            for (int mi = 0; mi < 2; mi++) {
                int r0 = warp_m * 32 + mi * 16 + (lane >> 2);
                int kk = kc + (lane & 3);
                af[mi][0] = __float_as_uint(As[buf][r0 * SA + kk]);
                af[mi][1] = __float_as_uint(As[buf][(r0 + 8) * SA + kk]);
                af[mi][2] = __float_as_uint(As[buf][r0 * SA + kk + 4]);
                af[mi][3] = __float_as_uint(As[buf][(r0 + 8) * SA + kk + 4]);
            }
#pragma unroll
            for (int ni = 0; ni < 8; ni++) {
                int col = warp_n * 64 + ni * 8 + (lane >> 2);
                uint32_t b0 = __float_as_uint(Ys[buf][(kc + (lane & 3)) * SY + col]);
                uint32_t b1 = __float_as_uint(Ys[buf][(kc + 4 + (lane & 3)) * SY + col]);
                mma_tf32(acc[0][ni], af[0], b0, b1);
                mma_tf32(acc[1][ni], af[1], b0, b1);
            }
        }

        if (hasNext) {
            uint4 o = make_uint4(f2tf32(aN.x), f2tf32(aN.y), f2tf32(aN.z), f2tf32(aN.w));
            *reinterpret_cast<uint4*>(&As[nbuf][ar * SA + ac]) = o;
            cp_wait0();
        }
        __syncthreads();
        buf = nbuf;
    }

    // ---- epilogue: scale by d_inv[row], store H ----
#pragma unroll
    for (int mi = 0; mi < 2; mi++) {
        int r0 = ctaM + warp_m * 32 + mi * 16 + (lane >> 2);
        float d0 = g_dinv[r0];
        float d1 = g_dinv[r0 + 8];
#pragma unroll
        for (int ni = 0; ni < 8; ni++) {
            int c0 = warp_n * 64 + ni * 8 + 2 * (lane & 3);
            float2 v0 = make_float2(acc[mi][ni][0] * d0, acc[mi][ni][1] * d0);
            float2 v1 = make_float2(acc[mi][ni][2] * d1, acc[mi][ni][3] * d1);
            *reinterpret_cast<float2*>(&g_H[(size_t)r0 * DIN + c0]) = v0;
            *reinterpret_cast<float2*>(&g_H[(size_t)(r0 + 8) * DIN + c0]) = v1;
        }
    }
}

// ---------------- kernel 4: out = H @ W^T (fp32 FFMA) -----------------------
// CTA 128x64, K-tile 32. grid (64, 4). Thread computes 8x4 outputs.
#define G2_BM 128
#define G2_BN 64
#define G2_BK 32
#define SH 36    // Hs row stride
#define SW 68    // Ws2 (transposed) row stride

__global__ __launch_bounds__(256) void gemm2_kernel(const float* __restrict__ W,
                                                    float* __restrict__ out) {
    __shared__ float Hs[G2_BM * SH];          // 18 KB
    __shared__ float Ws2[G2_BK * SW];         // 8.5 KB, layout [k][n]
    int t = threadIdx.x;
    int row0 = blockIdx.x * G2_BM;
    int col0 = blockIdx.y * G2_BN;
    int tm = t >> 4;          // 0..15 -> 8 rows each
    int tn = t & 15;          // 0..15 -> 4 cols each
    float acc[8][4];
#pragma unroll
    for (int i = 0; i < 8; i++)
#pragma unroll
        for (int j = 0; j < 4; j++) acc[i][j] = 0.0f;

    for (int k0 = 0; k0 < DIN; k0 += G2_BK) {
        // stage H tile: 128x32 floats = 1024 float4, 4 per thread
#pragma unroll
        for (int j = 0; j < 4; j++) {
            int v = j * 256 + t;
            int hr = v >> 3;
            int hc = (v & 7) * 4;
            *reinterpret_cast<float4*>(&Hs[hr * SH + hc]) =
                *reinterpret_cast<const float4*>(&g_H[(size_t)(row0 + hr) * DIN + k0 + hc]);
        }
        // stage W tile transposed: W[o][c] -> Ws2[c-k0][o-col0]; 512 float4/2 per thread
#pragma unroll
        for (int j = 0; j < 2; j++) {
            int v = j * 256 + t;
            int wr = v >> 3;                  // 0..63 (output col index)
            int wc = (v & 7) * 4;             // 0..28 (k index)
            float4 wv = *reinterpret_cast<const float4*>(&W[(size_t)(col0 + wr) * DIN + k0 + wc]);
            Ws2[(wc + 0) * SW + wr] = wv.x;
            Ws2[(wc + 1) * SW + wr] = wv.y;
            Ws2[(wc + 2) * SW + wr] = wv.z;
            Ws2[(wc + 3) * SW + wr] = wv.w;
        }
        __syncthreads();
#pragma unroll
        for (int k = 0; k < G2_BK; k++) {
            float h[8];
#pragma unroll
            for (int i = 0; i < 8; i++) h[i] = Hs[(tm * 8 + i) * SH + k];
            float4 wv = *reinterpret_cast<const float4*>(&Ws2[k * SW + tn * 4]);
            float w[4] = {wv.x, wv.y, wv.z, wv.w};
#pragma unroll
            for (int i = 0; i < 8; i++)
#pragma unroll
                for (int j = 0; j < 4; j++) acc[i][j] += h[i] * w[j];
        }
        __syncthreads();
    }
#pragma unroll
    for (int i = 0; i < 8; i++) {
        int r = row0 + tm * 8 + i;
        float4 v = make_float4(acc[i][0], acc[i][1], acc[i][2], acc[i][3]);
        *reinterpret_cast<float4*>(&out[(size_t)r * DOUT + col0 + tn * 4]) = v;
    }
}

// ---------------- launch ----------------------------------------------------
extern "C" void kernel_launch(void* const* d_in, const int* in_sizes, int n_in,
                              void* d_out, int out_size) {
    const float* X = (const float*)d_in[0];   // [8192, 256]
    const float* A = (const float*)d_in[1];   // [8192, 8192]
    const float* W = (const float*)d_in[2];   // [256, 256]
    float* out = (float*)d_out;               // [8192, 256]

    rowsum_kernel<<<NROW, 256>>>(A);
    prepY_kernel<<<(NROW * DIN / 4) / 256, 256>>>(X);
    gemm1_kernel<<<NROW / BM, 256>>>(A);
    dim3 g2(NROW / G2_BM, DOUT / G2_BN);
    gemm2_kernel<<<g2, 256>>>(W, out);
}

// round 9
// speedup vs baseline: 1.4808x; 1.4808x over previous
#include <cuda_runtime.h>
#include <cstdint>

#define NROW 8192
#define KDIM 8192
#define DIN  256
#define DOUT 256

// ---------------- scratch (static device globals; no allocations) ----------
__device__ float g_dinv[NROW];                 // 32 KB
__device__ float g_YT[(size_t)DIN * KDIM];     // 8 MB  Y^T[n][k] = tf32_rn(d_k * X[k][n])
__device__ float g_WT[DOUT * DIN];             // 256 KB W in tf32 (already [n][k])
__device__ float g_H[(size_t)NROW * DIN];      // 8 MB  A_norm @ X (fp32)

// ---------------- helpers ---------------------------------------------------
__device__ __forceinline__ uint32_t f2tf32(float x) {
    uint32_t r; asm("cvt.rna.tf32.f32 %0, %1;" : "=r"(r) : "f"(x)); return r;
}
__device__ __forceinline__ uint32_t smem_u32(const void* p) {
    uint32_t a;
    asm("{ .reg .u64 t; cvta.to.shared.u64 t, %1; cvt.u32.u64 %0, t; }" : "=r"(a) : "l"(p));
    return a;
}
__device__ __forceinline__ void cp16(uint32_t s, const void* g) {
    asm volatile("cp.async.cg.shared.global [%0], [%1], 16;" :: "r"(s), "l"(g));
}
__device__ __forceinline__ void cp_commit() { asm volatile("cp.async.commit_group;"); }
template <int N> __device__ __forceinline__ void cp_wait() {
    asm volatile("cp.async.wait_group %0;" :: "n"(N));
}

#define LDSM4(r, addr) \
    asm volatile("ldmatrix.sync.aligned.m8n8.x4.shared.b16 {%0,%1,%2,%3}, [%4];" \
                 : "=r"((r)[0]), "=r"((r)[1]), "=r"((r)[2]), "=r"((r)[3]) : "r"(addr))

__device__ __forceinline__ void mma_tf32(float (&c)[4], const uint32_t (&a)[4],
                                         uint32_t b0, uint32_t b1) {
    asm volatile(
        "mma.sync.aligned.m16n8k8.row.col.f32.tf32.tf32.f32 "
        "{%0,%1,%2,%3}, {%4,%5,%6,%7}, {%8,%9}, {%0,%1,%2,%3};\n"
        : "+f"(c[0]), "+f"(c[1]), "+f"(c[2]), "+f"(c[3])
        : "r"(a[0]), "r"(a[1]), "r"(a[2]), "r"(a[3]), "r"(b0), "r"(b1));
}

// ---------------- kernel 1: d_inv_sqrt = rsqrt(rowsum(A)) -------------------
__global__ __launch_bounds__(256) void rowsum_kernel(const float* __restrict__ A) {
    int row = blockIdx.x;
    const float4* a4 = reinterpret_cast<const float4*>(A + (size_t)row * KDIM);
    int t = threadIdx.x;
    float s = 0.0f;
#pragma unroll
    for (int j = 0; j < 8; j++) {
        float4 v = a4[t + 256 * j];
        s += (v.x + v.y) + (v.z + v.w);
    }
    __shared__ float red[256];
    red[t] = s;
    __syncthreads();
#pragma unroll
    for (int off = 128; off > 0; off >>= 1) {
        if (t < off) red[t] += red[t + off];
        __syncthreads();
    }
    if (t == 0) g_dinv[row] = rsqrtf(red[0]);
}

// ---------------- kernel 2: Y^T[n][k] = tf32_rn(d_k * X[k][n]) --------------
__global__ __launch_bounds__(256) void prepYT_kernel(const float* __restrict__ X) {
    __shared__ float ts[32][33];
    int k0 = blockIdx.x * 32, n0 = blockIdx.y * 32;
    int tx = threadIdx.x & 31, ty = threadIdx.x >> 5;   // ty 0..7
#pragma unroll
    for (int i = 0; i < 4; i++) {
        int k = k0 + ty + i * 8;
        float d = g_dinv[k];
        ts[ty + i * 8][tx] = __uint_as_float(f2tf32(X[(size_t)k * DIN + n0 + tx] * d));
    }
    __syncthreads();
#pragma unroll
    for (int i = 0; i < 4; i++) {
        int n = n0 + ty + i * 8;
        g_YT[(size_t)n * KDIM + k0 + tx] = ts[tx][ty + i * 8];
    }
}

// ---------------- kernel 2b: W -> tf32 (already [n][k] row-major) -----------
__global__ __launch_bounds__(256) void prepW_kernel(const float* __restrict__ W) {
    int idx = blockIdx.x * 256 + threadIdx.x;           // float4 index
    float4 v = reinterpret_cast<const float4*>(W)[idx];
    uint4 o;
    o.x = f2tf32(v.x); o.y = f2tf32(v.y); o.z = f2tf32(v.z); o.w = f2tf32(v.w);
    reinterpret_cast<uint4*>(g_WT)[idx] = o;
}

// ---------------- shared tf32-mma GEMM kernel -------------------------------
// C[m, 0:256] = scale(m) * A[m, :] @ B^T  with B given n-major as B[n][k].
// mode 0: A = adjacency (lda 8192), B = g_YT, C = g_H, scale = g_dinv, nk = 256
// mode 1: A = g_H (lda 256),       B = g_WT, C = out,  no scale,       nk = 8
// CTA: BM=64 rows, BN=256 (full), BK=32, 3-stage cp.async pipeline, 8 warps
// (2 m x 4 n), warp tile 32x64, fragments via ldmatrix.x4.
#define BM   64
#define BK   32
#define AST  36                   // floats per smem row (pad 32->36)
#define ARB  144                  // AST * 4 bytes
#define ASZ  (BM * ARB)           // 9216 B
#define BSZ  (256 * ARB)          // 36864 B
#define STG  (ASZ + BSZ)          // 46080 B
#define GSMEM (3 * STG)           // 138240 B

__device__ __forceinline__ void ldgA(float4 (&aR)[2], const float* Ag, size_t lda,
                                     int ctaM, int t, int k0) {
#pragma unroll
    for (int j = 0; j < 2; j++) {
        int v = t + 256 * j, row = v >> 3, c = v & 7;
        aR[j] = *reinterpret_cast<const float4*>(Ag + (size_t)(ctaM + row) * lda + k0 + c * 4);
    }
}
__device__ __forceinline__ void stsA(uint32_t abase, int t, const float4 (&aR)[2]) {
#pragma unroll
    for (int j = 0; j < 2; j++) {
        int v = t + 256 * j, row = v >> 3, c = v & 7;
        uint32_t x0 = f2tf32(aR[j].x), x1 = f2tf32(aR[j].y);
        uint32_t x2 = f2tf32(aR[j].z), x3 = f2tf32(aR[j].w);
        uint32_t d = abase + row * ARB + c * 16;
        asm volatile("st.shared.v4.b32 [%0], {%1,%2,%3,%4};"
                     :: "r"(d), "r"(x0), "r"(x1), "r"(x2), "r"(x3));
    }
}
__device__ __forceinline__ void cpB(uint32_t bbase, const float* Bg, size_t ldb,
                                    int t, int k0) {
#pragma unroll
    for (int j = 0; j < 8; j++) {
        int v = t + 256 * j, n = v >> 3, c = v & 7;
        cp16(bbase + n * ARB + c * 16, Bg + (size_t)n * ldb + k0 + c * 4);
    }
}

__global__ __launch_bounds__(256, 1)
void gemm_tc(const float* __restrict__ Aext, float* __restrict__ Cext, int mode) {
    extern __shared__ char smem[];
    uint32_t sb = smem_u32(smem);

    const float* Ag;  size_t lda;  const float* Bg;  size_t ldb;
    float* C;  const float* scale;  int nk;
    if (mode == 0) { Ag = Aext; lda = KDIM; Bg = g_YT; ldb = KDIM; C = g_H;  scale = g_dinv; nk = KDIM / BK; }
    else           { Ag = g_H;  lda = DIN;  Bg = g_WT; ldb = DIN;  C = Cext; scale = nullptr; nk = DIN / BK; }

    int t = threadIdx.x, wid = t >> 5, lane = t & 31;
    int warp_m = wid >> 2, warp_n = wid & 3;
    int ctaM = blockIdx.x * BM;

    float acc[2][8][4];
#pragma unroll
    for (int mi = 0; mi < 2; mi++)
#pragma unroll
        for (int ni = 0; ni < 8; ni++)
#pragma unroll
            for (int q = 0; q < 4; q++) acc[mi][ni][q] = 0.0f;

    // per-thread ldmatrix offsets (relative to stage base)
    int g = lane >> 3, r8 = lane & 7;
    uint32_t aoff = (uint32_t)(((g & 1) * 8 + r8) * ARB + (g >> 1) * 16);
    uint32_t boff = (uint32_t)(((g >> 1) * 8 + r8) * ARB + (g & 1) * 16) + ASZ;
    uint32_t aO0 = aoff + (warp_m * 32 + 0)  * ARB;
    uint32_t aO1 = aoff + (warp_m * 32 + 16) * ARB;
    uint32_t bO[4];
#pragma unroll
    for (int nj = 0; nj < 4; nj++) bO[nj] = boff + (warp_n * 64 + nj * 16) * ARB;

    // ---- prologue: stage tiles 0 and 1; tile 2 into regs ----
    float4 aR[2];
    ldgA(aR, Ag, lda, ctaM, t, 0);
    stsA(sb + 0 * STG, t, aR);
    cpB(sb + 0 * STG + ASZ, Bg, ldb, t, 0);
    cp_commit();
    ldgA(aR, Ag, lda, ctaM, t, BK);
    stsA(sb + 1 * STG, t, aR);
    cpB(sb + 1 * STG + ASZ, Bg, ldb, t, BK);
    cp_commit();
    ldgA(aR, Ag, lda, ctaM, t, 2 * BK);

    // ---- main loop ----
    for (int kt = 0; kt < nk; kt++) {
        cp_wait<1>();
        __syncthreads();

        int L = kt + 2;
        if (L < nk) {
            uint32_t stg = sb + (L % 3) * STG;
            stsA(stg, t, aR);
            if (L + 1 < nk) ldgA(aR, Ag, lda, ctaM, t, (L + 1) * BK);
            cpB(stg + ASZ, Bg, ldb, t, L * BK);
        }
        cp_commit();   // empty group near the tail keeps wait<1> accounting uniform

        uint32_t base = sb + (kt % 3) * STG;
        uint32_t a0 = base + aO0, a1 = base + aO1;
#pragma unroll
        for (int k8 = 0; k8 < 4; k8++) {
            uint32_t af0[4], af1[4];
            LDSM4(af0, a0 + k8 * 32);
            LDSM4(af1, a1 + k8 * 32);
#pragma unroll
            for (int nj = 0; nj < 4; nj++) {
                uint32_t bf[4];
                LDSM4(bf, base + bO[nj] + k8 * 32);
                mma_tf32(acc[0][2 * nj],     af0, bf[0], bf[1]);
                mma_tf32(acc[1][2 * nj],     af1, bf[0], bf[1]);
                mma_tf32(acc[0][2 * nj + 1], af0, bf[2], bf[3]);
                mma_tf32(acc[1][2 * nj + 1], af1, bf[2], bf[3]);
            }
        }
    }

    // ---- epilogue: optional row scale, store ----
#pragma unroll
    for (int mi = 0; mi < 2; mi++) {
        int r = ctaM + warp_m * 32 + mi * 16 + (lane >> 2);
        float s0 = scale ? scale[r] : 1.0f;
        float s1 = scale ? scale[r + 8] : 1.0f;
#pragma unroll
        for (int ni = 0; ni < 8; ni++) {
            int col = warp_n * 64 + ni * 8 + 2 * (lane & 3);
            float2 v0 = make_float2(acc[mi][ni][0] * s0, acc[mi][ni][1] * s0);
            float2 v1 = make_float2(acc[mi][ni][2] * s1, acc[mi][ni][3] * s1);
            *reinterpret_cast<float2*>(&C[(size_t)r * DIN + col]) = v0;
            *reinterpret_cast<float2*>(&C[(size_t)(r + 8) * DIN + col]) = v1;
        }
    }
}

// ---------------- launch ----------------------------------------------------
extern "C" void kernel_launch(void* const* d_in, const int* in_sizes, int n_in,
                              void* d_out, int out_size) {
    const float* X = (const float*)d_in[0];   // [8192, 256]
    const float* A = (const float*)d_in[1];   // [8192, 8192]
    const float* W = (const float*)d_in[2];   // [256, 256]
    float* out = (float*)d_out;               // [8192, 256]

    cudaFuncSetAttribute(gemm_tc, cudaFuncAttributeMaxDynamicSharedMemorySize, GSMEM);

    rowsum_kernel<<<NROW, 256>>>(A);
    prepYT_kernel<<<dim3(KDIM / 32, DIN / 32), 256>>>(X);
    prepW_kernel<<<(DOUT * DIN / 4) / 256, 256>>>(W);
    gemm_tc<<<NROW / BM, 256, GSMEM>>>(A, nullptr, 0);   // g_H = A_norm @ X
    gemm_tc<<<NROW / BM, 256, GSMEM>>>(nullptr, out, 1); // out = H @ W^T
}

// round 11
// speedup vs baseline: 1.5863x; 1.0713x over previous
#include <cuda_runtime.h>
#include <cstdint>

#define NROW 8192
#define KDIM 8192
#define DIN  256
#define DOUT 256

// ---------------- scratch (static device globals; no allocations) ----------
__device__ float g_dinv[NROW];                 // 32 KB
__device__ float g_YT[(size_t)DIN * KDIM];     // 8 MB  Y^T[n][k] = tf32_rn(d_k * X[k][n])
__device__ float g_WT[DOUT * DIN];             // 256 KB W in tf32 (already [n][k])
__device__ float g_H[(size_t)NROW * DIN];      // 8 MB  A_norm @ X (fp32)

// ---------------- helpers ---------------------------------------------------
__device__ __forceinline__ uint32_t f2tf32(float x) {
    uint32_t r; asm("cvt.rna.tf32.f32 %0, %1;" : "=r"(r) : "f"(x)); return r;
}
__device__ __forceinline__ uint32_t smem_u32(const void* p) {
    uint32_t a;
    asm("{ .reg .u64 t; cvta.to.shared.u64 t, %1; cvt.u32.u64 %0, t; }" : "=r"(a) : "l"(p));
    return a;
}
__device__ __forceinline__ void cp16(uint32_t s, const void* g) {
    asm volatile("cp.async.cg.shared.global [%0], [%1], 16;" :: "r"(s), "l"(g));
}
__device__ __forceinline__ void cp_commit() { asm volatile("cp.async.commit_group;"); }
template <int N> __device__ __forceinline__ void cp_wait() {
    asm volatile("cp.async.wait_group %0;" :: "n"(N));
}

#define LDSM4(r, addr) \
    asm volatile("ldmatrix.sync.aligned.m8n8.x4.shared.b16 {%0,%1,%2,%3}, [%4];" \
                 : "=r"((r)[0]), "=r"((r)[1]), "=r"((r)[2]), "=r"((r)[3]) : "r"(addr))

__device__ __forceinline__ void mma_tf32(float (&c)[4], const uint32_t (&a)[4],
                                         uint32_t b0, uint32_t b1) {
    asm volatile(
        "mma.sync.aligned.m16n8k8.row.col.f32.tf32.tf32.f32 "
        "{%0,%1,%2,%3}, {%4,%5,%6,%7}, {%8,%9}, {%0,%1,%2,%3};\n"
        : "+f"(c[0]), "+f"(c[1]), "+f"(c[2]), "+f"(c[3])
        : "r"(a[0]), "r"(a[1]), "r"(a[2]), "r"(a[3]), "r"(b0), "r"(b1));
}

// ---------------- kernel 1: d_inv_sqrt = rsqrt(rowsum(A)) -------------------
__global__ __launch_bounds__(256) void rowsum_kernel(const float* __restrict__ A) {
    int row = blockIdx.x;
    const float4* a4 = reinterpret_cast<const float4*>(A + (size_t)row * KDIM);
    int t = threadIdx.x;
    float s = 0.0f;
#pragma unroll
    for (int j = 0; j < 8; j++) {
        float4 v = a4[t + 256 * j];
        s += (v.x + v.y) + (v.z + v.w);
    }
    __shared__ float red[256];
    red[t] = s;
    __syncthreads();
#pragma unroll
    for (int off = 128; off > 0; off >>= 1) {
        if (t < off) red[t] += red[t + off];
        __syncthreads();
    }
    if (t == 0) g_dinv[row] = rsqrtf(red[0]);
}

// ---------------- kernel 2: Y^T[n][k] = tf32_rn(d_k * X[k][n]) --------------
__global__ __launch_bounds__(256) void prepYT_kernel(const float* __restrict__ X) {
    __shared__ float ts[32][33];
    int k0 = blockIdx.x * 32, n0 = blockIdx.y * 32;
    int tx = threadIdx.x & 31, ty = threadIdx.x >> 5;   // ty 0..7
#pragma unroll
    for (int i = 0; i < 4; i++) {
        int k = k0 + ty + i * 8;
        float d = g_dinv[k];
        ts[ty + i * 8][tx] = __uint_as_float(f2tf32(X[(size_t)k * DIN + n0 + tx] * d));
    }
    __syncthreads();
#pragma unroll
    for (int i = 0; i < 4; i++) {
        int n = n0 + ty + i * 8;
        g_YT[(size_t)n * KDIM + k0 + tx] = ts[tx][ty + i * 8];
    }
}

// ---------------- kernel 2b: W -> tf32 (already [n][k] row-major) -----------
__global__ __launch_bounds__(256) void prepW_kernel(const float* __restrict__ W) {
    int idx = blockIdx.x * 256 + threadIdx.x;           // float4 index
    float4 v = reinterpret_cast<const float4*>(W)[idx];
    uint4 o;
    o.x = f2tf32(v.x); o.y = f2tf32(v.y); o.z = f2tf32(v.z); o.w = f2tf32(v.w);
    reinterpret_cast<uint4*>(g_WT)[idx] = o;
}

// ---------------- shared tf32-mma GEMM kernel -------------------------------
// C[m, 0:256] = scale(m) * A[m, :] @ B^T  with B given n-major as B[n][k].
// mode 0: A = adjacency (lda 8192), B = g_YT, C = g_H, scale = g_dinv, nk = 256
// mode 1: A = g_H (lda 256),       B = g_WT, C = out,  no scale,       nk = 8
// CTA: BM=64 rows, BN=256 (full), BK=32, 3-stage cp.async pipeline, 8 warps
// (2 m x 4 n), warp tile 32x64, fragments via ldmatrix.x4, k8-double-buffered.
#define BM   64
#define BK   32
#define AST  36                   // floats per smem row (pad 32->36)
#define ARB  144                  // AST * 4 bytes
#define ASZ  (BM * ARB)           // 9216 B
#define BSZ  (256 * ARB)          // 36864 B
#define STG  (ASZ + BSZ)          // 46080 B
#define GSMEM (3 * STG)           // 138240 B

__device__ __forceinline__ void ldgA(float4 (&aR)[2], const float* Ag, size_t lda,
                                     int ctaM, int t, int k0) {
#pragma unroll
    for (int j = 0; j < 2; j++) {
        int v = t + 256 * j, row = v >> 3, c = v & 7;
        aR[j] = *reinterpret_cast<const float4*>(Ag + (size_t)(ctaM + row) * lda + k0 + c * 4);
    }
}
__device__ __forceinline__ void stsA(uint32_t abase, int t, const float4 (&aR)[2]) {
#pragma unroll
    for (int j = 0; j < 2; j++) {
        int v = t + 256 * j, row = v >> 3, c = v & 7;
        uint32_t x0 = f2tf32(aR[j].x), x1 = f2tf32(aR[j].y);
        uint32_t x2 = f2tf32(aR[j].z), x3 = f2tf32(aR[j].w);
        uint32_t d = abase + row * ARB + c * 16;
        asm volatile("st.shared.v4.b32 [%0], {%1,%2,%3,%4};"
                     :: "r"(d), "r"(x0), "r"(x1), "r"(x2), "r"(x3));
    }
}
__device__ __forceinline__ void cpB(uint32_t bbase, const float* Bg, size_t ldb,
                                    int t, int k0) {
#pragma unroll
    for (int j = 0; j < 8; j++) {
        int v = t + 256 * j, n = v >> 3, c = v & 7;
        cp16(bbase + n * ARB + c * 16, Bg + (size_t)n * ldb + k0 + c * 4);
    }
}

__global__ __launch_bounds__(256, 1)
void gemm_tc(const float* __restrict__ Aext, float* __restrict__ Cext, int mode) {
    extern __shared__ char smem[];
    uint32_t sb = smem_u32(smem);

    const float* Ag;  size_t lda;  const float* Bg;  size_t ldb;
    float* C;  const float* scale;  int nk;
    if (mode == 0) { Ag = Aext; lda = KDIM; Bg = g_YT; ldb = KDIM; C = g_H;  scale = g_dinv; nk = KDIM / BK; }
    else           { Ag = g_H;  lda = DIN;  Bg = g_WT; ldb = DIN;  C = Cext; scale = nullptr; nk = DIN / BK; }

    int t = threadIdx.x, wid = t >> 5, lane = t & 31;
    int warp_m = wid >> 2, warp_n = wid & 3;
    int ctaM = blockIdx.x * BM;

    float acc[2][8][4];
#pragma unroll
    for (int mi = 0; mi < 2; mi++)
#pragma unroll
        for (int ni = 0; ni < 8; ni++)
#pragma unroll
            for (int q = 0; q < 4; q++) acc[mi][ni][q] = 0.0f;

    // per-thread ldmatrix offsets (relative to stage base)
    int g = lane >> 3, r8 = lane & 7;
    uint32_t aoff = (uint32_t)(((g & 1) * 8 + r8) * ARB + (g >> 1) * 16);
    uint32_t boff = (uint32_t)(((g >> 1) * 8 + r8) * ARB + (g & 1) * 16) + ASZ;
    uint32_t aO0 = aoff + (warp_m * 32 + 0)  * ARB;
    uint32_t aO1 = aoff + (warp_m * 32 + 16) * ARB;
    uint32_t bO[4];
#pragma unroll
    for (int nj = 0; nj < 4; nj++) bO[nj] = boff + (warp_n * 64 + nj * 16) * ARB;

    // ---- prologue: stage tiles 0 and 1; tile 2 into regs ----
    float4 aR[2];
    ldgA(aR, Ag, lda, ctaM, t, 0);
    stsA(sb + 0 * STG, t, aR);
    cpB(sb + 0 * STG + ASZ, Bg, ldb, t, 0);
    cp_commit();
    ldgA(aR, Ag, lda, ctaM, t, BK);
    stsA(sb + 1 * STG, t, aR);
    cpB(sb + 1 * STG + ASZ, Bg, ldb, t, BK);
    cp_commit();
    ldgA(aR, Ag, lda, ctaM, t, 2 * BK);

    // fragment double buffers (k8-level software pipeline)
    uint32_t af[2][2][4];     // [buf][mi][reg]
    uint32_t bf[2][4][4];     // [buf][nj][reg]

    // ---- main loop ----
    for (int kt = 0; kt < nk; kt++) {
        cp_wait<1>();
        __syncthreads();

        uint32_t base = sb + (kt % 3) * STG;
        uint32_t a0 = base + aO0, a1 = base + aO1;

        // prefetch k8=0 fragments first: their LDS latency hides behind staging issue
        LDSM4(af[0][0], a0);
        LDSM4(af[0][1], a1);
#pragma unroll
        for (int nj = 0; nj < 4; nj++) LDSM4(bf[0][nj], base + bO[nj]);

        // stage tile L = kt + 2
        int L = kt + 2;
        if (L < nk) {
            uint32_t stg = sb + (L % 3) * STG;
            stsA(stg, t, aR);
            if (L + 1 < nk) ldgA(aR, Ag, lda, ctaM, t, (L + 1) * BK);
            cpB(stg + ASZ, Bg, ldb, t, L * BK);
        }
        cp_commit();   // empty group near the tail keeps wait<1> accounting uniform

        // compute: 4 k8 steps, double-buffered fragments
#pragma unroll
        for (int k8 = 0; k8 < 4; k8++) {
            int cur = k8 & 1, nxt = cur ^ 1;
            if (k8 < 3) {
                LDSM4(af[nxt][0], a0 + (k8 + 1) * 32);
                LDSM4(af[nxt][1], a1 + (k8 + 1) * 32);
#pragma unroll
                for (int nj = 0; nj < 4; nj++)
                    LDSM4(bf[nxt][nj], base + bO[nj] + (k8 + 1) * 32);
            }
#pragma unroll
            for (int nj = 0; nj < 4; nj++) {
                mma_tf32(acc[0][2 * nj],     af[cur][0], bf[cur][nj][0], bf[cur][nj][1]);
                mma_tf32(acc[1][2 * nj],     af[cur][1], bf[cur][nj][0], bf[cur][nj][1]);
                mma_tf32(acc[0][2 * nj + 1], af[cur][0], bf[cur][nj][2], bf[cur][nj][3]);
                mma_tf32(acc[1][2 * nj + 1], af[cur][1], bf[cur][nj][2], bf[cur][nj][3]);
            }
        }
    }

    // ---- epilogue: optional row scale, store ----
#pragma unroll
    for (int mi = 0; mi < 2; mi++) {
        int r = ctaM + warp_m * 32 + mi * 16 + (lane >> 2);
        float s0 = scale ? scale[r] : 1.0f;
        float s1 = scale ? scale[r + 8] : 1.0f;
#pragma unroll
        for (int ni = 0; ni < 8; ni++) {
            int col = warp_n * 64 + ni * 8 + 2 * (lane & 3);
            float2 v0 = make_float2(acc[mi][ni][0] * s0, acc[mi][ni][1] * s0);
            float2 v1 = make_float2(acc[mi][ni][2] * s1, acc[mi][ni][3] * s1);
            *reinterpret_cast<float2*>(&C[(size_t)r * DIN + col]) = v0;
            *reinterpret_cast<float2*>(&C[(size_t)(r + 8) * DIN + col]) = v1;
        }
    }
}

// ---------------- launch ----------------------------------------------------
extern "C" void kernel_launch(void* const* d_in, const int* in_sizes, int n_in,
                              void* d_out, int out_size) {
    const float* X = (const float*)d_in[0];   // [8192, 256]
    const float* A = (const float*)d_in[1];   // [8192, 8192]
    const float* W = (const float*)d_in[2];   // [256, 256]
    float* out = (float*)d_out;               // [8192, 256]

    cudaFuncSetAttribute(gemm_tc, cudaFuncAttributeMaxDynamicSharedMemorySize, GSMEM);

    rowsum_kernel<<<NROW, 256>>>(A);
    prepYT_kernel<<<dim3(KDIM / 32, DIN / 32), 256>>>(X);
    prepW_kernel<<<(DOUT * DIN / 4) / 256, 256>>>(W);
    gemm_tc<<<NROW / BM, 256, GSMEM>>>(A, nullptr, 0);   // g_H = A_norm @ X
    gemm_tc<<<NROW / BM, 256, GSMEM>>>(nullptr, out, 1); // out = H @ W^T
}

// round 13
// speedup vs baseline: 1.6211x; 1.0219x over previous
#include <cuda_runtime.h>
#include <cstdint>

#define NROW 8192
#define KDIM 8192
#define DIN  256
#define DOUT 256

// ---------------- scratch (static device globals; no allocations) ----------
__device__ float g_dinv[NROW];                 // 32 KB
__device__ float g_YT[(size_t)DIN * KDIM];     // 8 MB  Y^T[n][k] = tf32_rn(d_k * X[k][n])
__device__ float g_WT[DOUT * DIN];             // 256 KB W in tf32 (already [n][k])
__device__ float g_H[(size_t)NROW * DIN];      // 8 MB  A_norm @ X (fp32)

// ---------------- helpers ---------------------------------------------------
__device__ __forceinline__ uint32_t f2tf32(float x) {
    uint32_t r; asm("cvt.rna.tf32.f32 %0, %1;" : "=r"(r) : "f"(x)); return r;
}
__device__ __forceinline__ uint32_t smem_u32(const void* p) {
    uint32_t a;
    asm("{ .reg .u64 t; cvta.to.shared.u64 t, %1; cvt.u32.u64 %0, t; }" : "=r"(a) : "l"(p));
    return a;
}
__device__ __forceinline__ void cp16(uint32_t s, const void* g) {
    asm volatile("cp.async.cg.shared.global [%0], [%1], 16;" :: "r"(s), "l"(g));
}
__device__ __forceinline__ void cp_commit() { asm volatile("cp.async.commit_group;"); }
template <int N> __device__ __forceinline__ void cp_wait() {
    asm volatile("cp.async.wait_group %0;" :: "n"(N));
}

#define LDSM4(r, addr) \
    asm volatile("ldmatrix.sync.aligned.m8n8.x4.shared.b16 {%0,%1,%2,%3}, [%4];" \
                 : "=r"((r)[0]), "=r"((r)[1]), "=r"((r)[2]), "=r"((r)[3]) : "r"(addr))

__device__ __forceinline__ void mma_tf32(float (&c)[4], const uint32_t (&a)[4],
                                         uint32_t b0, uint32_t b1) {
    asm volatile(
        "mma.sync.aligned.m16n8k8.row.col.f32.tf32.tf32.f32 "
        "{%0,%1,%2,%3}, {%4,%5,%6,%7}, {%8,%9}, {%0,%1,%2,%3};\n"
        : "+f"(c[0]), "+f"(c[1]), "+f"(c[2]), "+f"(c[3])
        : "r"(a[0]), "r"(a[1]), "r"(a[2]), "r"(a[3]), "r"(b0), "r"(b1));
}

// ---------------- kernel 1: d_inv_sqrt = rsqrt(rowsum(A)) -------------------
__global__ __launch_bounds__(256) void rowsum_kernel(const float* __restrict__ A) {
    int row = blockIdx.x;
    const float4* a4 = reinterpret_cast<const float4*>(A + (size_t)row * KDIM);
    int t = threadIdx.x;
    float s = 0.0f;
#pragma unroll
    for (int j = 0; j < 8; j++) {
        float4 v = a4[t + 256 * j];
        s += (v.x + v.y) + (v.z + v.w);
    }
    __shared__ float red[256];
    red[t] = s;
    __syncthreads();
#pragma unroll
    for (int off = 128; off > 0; off >>= 1) {
        if (t < off) red[t] += red[t + off];
        __syncthreads();
    }
    if (t == 0) g_dinv[row] = rsqrtf(red[0]);
}

// ---------------- kernel 2: Y^T[n][k] = tf32_rn(d_k * X[k][n]) --------------
__global__ __launch_bounds__(256) void prepYT_kernel(const float* __restrict__ X) {
    __shared__ float ts[32][33];
    int k0 = blockIdx.x * 32, n0 = blockIdx.y * 32;
    int tx = threadIdx.x & 31, ty = threadIdx.x >> 5;   // ty 0..7
#pragma unroll
    for (int i = 0; i < 4; i++) {
        int k = k0 + ty + i * 8;
        float d = g_dinv[k];
        ts[ty + i * 8][tx] = __uint_as_float(f2tf32(X[(size_t)k * DIN + n0 + tx] * d));
    }
    __syncthreads();
#pragma unroll
    for (int i = 0; i < 4; i++) {
        int n = n0 + ty + i * 8;
        g_YT[(size_t)n * KDIM + k0 + tx] = ts[tx][ty + i * 8];
    }
}

// ---------------- kernel 2b: W -> tf32 (already [n][k] row-major) -----------
__global__ __launch_bounds__(256) void prepW_kernel(const float* __restrict__ W) {
    int idx = blockIdx.x * 256 + threadIdx.x;           // float4 index
    float4 v = reinterpret_cast<const float4*>(W)[idx];
    uint4 o;
    o.x = f2tf32(v.x); o.y = f2tf32(v.y); o.z = f2tf32(v.z); o.w = f2tf32(v.w);
    reinterpret_cast<uint4*>(g_WT)[idx] = o;
}

// ---------------- shared tf32-mma GEMM kernel -------------------------------
// C[m, 0:256] = scale(m) * A[m, :] @ B^T  with B given n-major as B[n][k].
// mode 0: A = adjacency (lda 8192), B = g_YT, C = g_H, scale = g_dinv, nk = 256
// mode 1: A = g_H (lda 256),       B = g_WT, C = out,  no scale,       nk = 8
// CTA: 512 threads, 16 warps (2m x 8n), warp tile 32x32.
// BM=64, BN=256, BK=32, 3-stage cp.async ring, ldmatrix.x4, k8 double-buffer.
#define BM   64
#define BK   32
#define AST  36                   // floats per smem row (pad 32->36)
#define ARB  144                  // AST * 4 bytes
#define ASZ  (BM * ARB)           // 9216 B
#define BSZ  (256 * ARB)          // 36864 B
#define STG  (ASZ + BSZ)          // 46080 B
#define GSMEM (3 * STG)           // 138240 B
#define NT   512

__device__ __forceinline__ void ldgA(float4& aR, const float* Ag, size_t lda,
                                     int ctaM, int t, int k0) {
    int row = t >> 3, c = t & 7;   // 512 threads -> 64 rows x 8 chunks
    aR = *reinterpret_cast<const float4*>(Ag + (size_t)(ctaM + row) * lda + k0 + c * 4);
}
__device__ __forceinline__ void stsA(uint32_t abase, int t, const float4& aR) {
    int row = t >> 3, c = t & 7;
    uint32_t x0 = f2tf32(aR.x), x1 = f2tf32(aR.y);
    uint32_t x2 = f2tf32(aR.z), x3 = f2tf32(aR.w);
    uint32_t d = abase + row * ARB + c * 16;
    asm volatile("st.shared.v4.b32 [%0], {%1,%2,%3,%4};"
                 :: "r"(d), "r"(x0), "r"(x1), "r"(x2), "r"(x3));
}
__device__ __forceinline__ void cpB(uint32_t bbase, const float* Bg, size_t ldb,
                                    int t, int k0) {
#pragma unroll
    for (int j = 0; j < 4; j++) {
        int v = t + NT * j, n = v >> 3, c = v & 7;
        cp16(bbase + n * ARB + c * 16, Bg + (size_t)n * ldb + k0 + c * 4);
    }
}

__global__ __launch_bounds__(NT, 1)
void gemm_tc(const float* __restrict__ Aext, float* __restrict__ Cext, int mode) {
    extern __shared__ char smem[];
    uint32_t sb = smem_u32(smem);

    const float* Ag;  size_t lda;  const float* Bg;  size_t ldb;
    float* C;  const float* scale;  int nk;
    if (mode == 0) { Ag = Aext; lda = KDIM; Bg = g_YT; ldb = KDIM; C = g_H;  scale = g_dinv; nk = KDIM / BK; }
    else           { Ag = g_H;  lda = DIN;  Bg = g_WT; ldb = DIN;  C = Cext; scale = nullptr; nk = DIN / BK; }

    int t = threadIdx.x, wid = t >> 5, lane = t & 31;
    int warp_m = wid >> 3, warp_n = wid & 7;    // 2 x 8
    int ctaM = blockIdx.x * BM;

    float acc[2][4][4];                         // [mi][ni][reg], warp tile 32x32
#pragma unroll
    for (int mi = 0; mi < 2; mi++)
#pragma unroll
        for (int ni = 0; ni < 4; ni++)
#pragma unroll
            for (int q = 0; q < 4; q++) acc[mi][ni][q] = 0.0f;

    // per-thread ldmatrix offsets (relative to stage base)
    int g = lane >> 3, r8 = lane & 7;
    uint32_t aoff = (uint32_t)(((g & 1) * 8 + r8) * ARB + (g >> 1) * 16);
    uint32_t boff = (uint32_t)(((g >> 1) * 8 + r8) * ARB + (g & 1) * 16) + ASZ;
    uint32_t aO0 = aoff + (warp_m * 32 + 0)  * ARB;
    uint32_t aO1 = aoff + (warp_m * 32 + 16) * ARB;
    uint32_t bO0 = boff + (warp_n * 32 + 0)  * ARB;
    uint32_t bO1 = boff + (warp_n * 32 + 16) * ARB;

    // ---- prologue: stage tiles 0 and 1; tile 2 into regs ----
    float4 aR;
    ldgA(aR, Ag, lda, ctaM, t, 0);
    stsA(sb + 0 * STG, t, aR);
    cpB(sb + 0 * STG + ASZ, Bg, ldb, t, 0);
    cp_commit();
    ldgA(aR, Ag, lda, ctaM, t, BK);
    stsA(sb + 1 * STG, t, aR);
    cpB(sb + 1 * STG + ASZ, Bg, ldb, t, BK);
    cp_commit();
    ldgA(aR, Ag, lda, ctaM, t, 2 * BK);

    // fragment double buffers (k8-level software pipeline)
    uint32_t af[2][2][4];     // [buf][mi][reg]
    uint32_t bf[2][2][4];     // [buf][nhalf][reg]

    // ---- main loop ----
    for (int kt = 0; kt < nk; kt++) {
        cp_wait<1>();
        __syncthreads();

        uint32_t base = sb + (kt % 3) * STG;
        uint32_t a0 = base + aO0, a1 = base + aO1;
        uint32_t b0 = base + bO0, b1 = base + bO1;

        // prefetch k8=0 fragments; latency hides behind staging issue below
        LDSM4(af[0][0], a0);
        LDSM4(af[0][1], a1);
        LDSM4(bf[0][0], b0);
        LDSM4(bf[0][1], b1);

        // stage tile L = kt + 2
        int L = kt + 2;
        if (L < nk) {
            uint32_t stg = sb + (L % 3) * STG;
            stsA(stg, t, aR);
            if (L + 1 < nk) ldgA(aR, Ag, lda, ctaM, t, (L + 1) * BK);
            cpB(stg + ASZ, Bg, ldb, t, L * BK);
        }
        cp_commit();   // empty group near the tail keeps wait<1> accounting uniform

        // compute: 4 k8 steps, double-buffered fragments, 8 MMAs each
#pragma unroll
        for (int k8 = 0; k8 < 4; k8++) {
            int cur = k8 & 1, nxt = cur ^ 1;
            if (k8 < 3) {
                LDSM4(af[nxt][0], a0 + (k8 + 1) * 32);
                LDSM4(af[nxt][1], a1 + (k8 + 1) * 32);
                LDSM4(bf[nxt][0], b0 + (k8 + 1) * 32);
                LDSM4(bf[nxt][1], b1 + (k8 + 1) * 32);
            }
#pragma unroll
            for (int nj = 0; nj < 2; nj++) {
                mma_tf32(acc[0][2 * nj],     af[cur][0], bf[cur][nj][0], bf[cur][nj][1]);
                mma_tf32(acc[1][2 * nj],     af[cur][1], bf[cur][nj][0], bf[cur][nj][1]);
                mma_tf32(acc[0][2 * nj + 1], af[cur][0], bf[cur][nj][2], bf[cur][nj][3]);
                mma_tf32(acc[1][2 * nj + 1], af[cur][1], bf[cur][nj][2], bf[cur][nj][3]);
            }
        }
    }

    // ---- epilogue: optional row scale, store ----
#pragma unroll
    for (int mi = 0; mi < 2; mi++) {
        int r = ctaM + warp_m * 32 + mi * 16 + (lane >> 2);
        float s0 = scale ? scale[r] : 1.0f;
        float s1 = scale ? scale[r + 8] : 1.0f;
#pragma unroll
        for (int ni = 0; ni < 4; ni++) {
            int col = warp_n * 32 + ni * 8 + 2 * (lane & 3);
            float2 v0 = make_float2(acc[mi][ni][0] * s0, acc[mi][ni][1] * s0);
            float2 v1 = make_float2(acc[mi][ni][2] * s1, acc[mi][ni][3] * s1);
            *reinterpret_cast<float2*>(&C[(size_t)r * DIN + col]) = v0;
            *reinterpret_cast<float2*>(&C[(size_t)(r + 8) * DIN + col]) = v1;
        }
    }
}

// ---------------- launch ----------------------------------------------------
extern "C" void kernel_launch(void* const* d_in, const int* in_sizes, int n_in,
                              void* d_out, int out_size) {
    const float* X = (const float*)d_in[0];   // [8192, 256]
    const float* A = (const float*)d_in[1];   // [8192, 8192]
    const float* W = (const float*)d_in[2];   // [256, 256]
    float* out = (float*)d_out;               // [8192, 256]

    cudaFuncSetAttribute(gemm_tc, cudaFuncAttributeMaxDynamicSharedMemorySize, GSMEM);

    rowsum_kernel<<<NROW, 256>>>(A);
    prepYT_kernel<<<dim3(KDIM / 32, DIN / 32), 256>>>(X);
    prepW_kernel<<<(DOUT * DIN / 4) / 256, 256>>>(W);
    gemm_tc<<<NROW / BM, NT, GSMEM>>>(A, nullptr, 0);   // g_H = A_norm @ X
    gemm_tc<<<NROW / BM, NT, GSMEM>>>(nullptr, out, 1); // out = H @ W^T
}

// round 15
// speedup vs baseline: 2.5988x; 1.6032x over previous
#include <cuda_runtime.h>
#include <cuda_fp16.h>
#include <cstdint>

#define NROW 8192
#define KDIM 8192
#define DIN  256
#define DOUT 256

// ---------------- scratch (static device globals; no allocations) ----------
__device__ float  g_dinv[NROW];                  // 32 KB
__device__ __half g_YT[(size_t)DIN * KDIM];      // 4 MB  Y^T[n][k] = h(d_k * X[k][n])
__device__ __half g_WT[DOUT * DIN];              // 128 KB W in half ([n][k] already)
__device__ float  g_H[(size_t)NROW * DIN];       // 8 MB  A_norm @ X (fp32)

// ---------------- helpers ---------------------------------------------------
__device__ __forceinline__ uint32_t f2h2(float a, float b) {
    uint32_t r;
    asm("cvt.rn.f16x2.f32 %0, %2, %1;" : "=r"(r) : "f"(a), "f"(b));
    return r;   // lo half = a, hi half = b
}
__device__ __forceinline__ uint32_t smem_u32(const void* p) {
    uint32_t a;
    asm("{ .reg .u64 t; cvta.to.shared.u64 t, %1; cvt.u32.u64 %0, t; }" : "=r"(a) : "l"(p));
    return a;
}
__device__ __forceinline__ void cp16(uint32_t s, const void* g) {
    asm volatile("cp.async.cg.shared.global [%0], [%1], 16;" :: "r"(s), "l"(g));
}
__device__ __forceinline__ void cp_commit() { asm volatile("cp.async.commit_group;"); }
template <int N> __device__ __forceinline__ void cp_wait() {
    asm volatile("cp.async.wait_group %0;" :: "n"(N));
}

#define LDSM4(r, addr) \
    asm volatile("ldmatrix.sync.aligned.m8n8.x4.shared.b16 {%0,%1,%2,%3}, [%4];" \
                 : "=r"((r)[0]), "=r"((r)[1]), "=r"((r)[2]), "=r"((r)[3]) : "r"(addr))

// m16n8k16 fp16 MMA, fp32 accumulate: 2048 MACs/instruction
__device__ __forceinline__ void mma_f16(float (&c)[4], const uint32_t (&a)[4],
                                        uint32_t b0, uint32_t b1) {
    asm volatile(
        "mma.sync.aligned.m16n8k16.row.col.f32.f16.f16.f32 "
        "{%0,%1,%2,%3}, {%4,%5,%6,%7}, {%8,%9}, {%0,%1,%2,%3};\n"
        : "+f"(c[0]), "+f"(c[1]), "+f"(c[2]), "+f"(c[3])
        : "r"(a[0]), "r"(a[1]), "r"(a[2]), "r"(a[3]), "r"(b0), "r"(b1));
}

// ---------------- kernel 1: d_inv_sqrt = rsqrt(rowsum(A)) -------------------
__global__ __launch_bounds__(256) void rowsum_kernel(const float* __restrict__ A) {
    int row = blockIdx.x;
    const float4* a4 = reinterpret_cast<const float4*>(A + (size_t)row * KDIM);
    int t = threadIdx.x;
    float s = 0.0f;
#pragma unroll
    for (int j = 0; j < 8; j++) {
        float4 v = a4[t + 256 * j];
        s += (v.x + v.y) + (v.z + v.w);
    }
    __shared__ float red[256];
    red[t] = s;
    __syncthreads();
#pragma unroll
    for (int off = 128; off > 0; off >>= 1) {
        if (t < off) red[t] += red[t + off];
        __syncthreads();
    }
    if (t == 0) g_dinv[row] = rsqrtf(red[0]);
}

// ---------------- kernel 2: Y^T[n][k] = h(d_k * X[k][n]) --------------------
__global__ __launch_bounds__(256) void prepYT_kernel(const float* __restrict__ X) {
    __shared__ float ts[32][33];
    int k0 = blockIdx.x * 32, n0 = blockIdx.y * 32;
    int tx = threadIdx.x & 31, ty = threadIdx.x >> 5;   // ty 0..7
#pragma unroll
    for (int i = 0; i < 4; i++) {
        int k = k0 + ty + i * 8;
        float d = g_dinv[k];
        ts[ty + i * 8][tx] = X[(size_t)k * DIN + n0 + tx] * d;
    }
    __syncthreads();
#pragma unroll
    for (int i = 0; i < 4; i++) {
        int n = n0 + ty + i * 8;
        g_YT[(size_t)n * KDIM + k0 + tx] = __float2half_rn(ts[tx][ty + i * 8]);
    }
}

// ---------------- kernel 2b: W -> half ([n][k] row-major already) -----------
__global__ __launch_bounds__(256) void prepW_kernel(const float* __restrict__ W) {
    int idx = blockIdx.x * 256 + threadIdx.x;           // float4 index
    float4 v = reinterpret_cast<const float4*>(W)[idx];
    uint2 o;
    o.x = f2h2(v.x, v.y);
    o.y = f2h2(v.z, v.w);
    reinterpret_cast<uint2*>(g_WT)[idx] = o;
}

// ---------------- shared fp16-mma GEMM kernel -------------------------------
// C[m, 0:256] = scale(m) * A[m, :] @ B^T, B given n-major as half B[n][k].
// mode 0: A = adjacency (lda 8192), B = g_YT, C = g_H, scale = g_dinv, nk = 128
// mode 1: A = g_H (lda 256),       B = g_WT, C = out,  no scale,       nk = 4
// CTA: 512 threads, 16 warps (2m x 8n), warp tile 32x32, m16n8k16 fp16.
// BM=64, BN=256, BK=64, 3-stage cp.async ring, ldmatrix.x4, k16 double-buffer.
#define BM   64
#define BK   64
#define ARB  144                  // smem row stride bytes: 64 halfs + 16B pad
#define ASZ  (BM * ARB)           // 9216 B
#define BSZ  (256 * ARB)          // 36864 B
#define STG  (ASZ + BSZ)          // 46080 B
#define GSMEM (3 * STG)           // 138240 B
#define NT   512

__device__ __forceinline__ void ldgA(float4 (&aR)[2], const float* Ag, size_t lda,
                                     int ctaM, int t, int k0) {
    int row = t >> 3, c = t & 7;   // 64 rows x 8 chunks of 8 floats
    const float* p = Ag + (size_t)(ctaM + row) * lda + k0 + c * 8;
    aR[0] = *reinterpret_cast<const float4*>(p);
    aR[1] = *reinterpret_cast<const float4*>(p + 4);
}
__device__ __forceinline__ void stsA(uint32_t abase, int t, const float4 (&aR)[2]) {
    int row = t >> 3, c = t & 7;
    uint32_t h0 = f2h2(aR[0].x, aR[0].y), h1 = f2h2(aR[0].z, aR[0].w);
    uint32_t h2 = f2h2(aR[1].x, aR[1].y), h3 = f2h2(aR[1].z, aR[1].w);
    uint32_t d = abase + row * ARB + c * 16;
    asm volatile("st.shared.v4.b32 [%0], {%1,%2,%3,%4};"
                 :: "r"(d), "r"(h0), "r"(h1), "r"(h2), "r"(h3));
}
__device__ __forceinline__ void cpB(uint32_t bbase, const __half* Bg, size_t ldb,
                                    int t, int k0) {
#pragma unroll
    for (int j = 0; j < 4; j++) {
        int v = t + NT * j, n = v >> 3, c = v & 7;    // 256 rows x 8 chunks of 8 halfs
        cp16(bbase + n * ARB + c * 16, Bg + (size_t)n * ldb + k0 + c * 8);
    }
}

__global__ __launch_bounds__(NT, 1)
void gemm_tc(const float* __restrict__ Aext, float* __restrict__ Cext, int mode) {
    extern __shared__ char smem[];
    uint32_t sb = smem_u32(smem);

    const float* Ag;  size_t lda;  const __half* Bg;  size_t ldb;
    float* C;  const float* scale;  int nk;
    if (mode == 0) { Ag = Aext; lda = KDIM; Bg = g_YT; ldb = KDIM; C = g_H;  scale = g_dinv; nk = KDIM / BK; }
    else           { Ag = g_H;  lda = DIN;  Bg = g_WT; ldb = DIN;  C = Cext; scale = nullptr; nk = DIN / BK; }

    int t = threadIdx.x, wid = t >> 5, lane = t & 31;
    int warp_m = wid >> 3, warp_n = wid & 7;    // 2 x 8
    int ctaM = blockIdx.x * BM;

    float acc[2][4][4];                         // [mi][ni][reg], warp tile 32x32
#pragma unroll
    for (int mi = 0; mi < 2; mi++)
#pragma unroll
        for (int ni = 0; ni < 4; ni++)
#pragma unroll
            for (int q = 0; q < 4; q++) acc[mi][ni][q] = 0.0f;

    // per-thread ldmatrix offsets (relative to stage base)
    // A (16x16 tile via x4): lane l -> row (l % 16), byte (l/16)*16
    uint32_t aO0 = (uint32_t)((warp_m * 32 + 0  + (lane & 15)) * ARB + (lane >> 4) * 16);
    uint32_t aO1 = (uint32_t)((warp_m * 32 + 16 + (lane & 15)) * ARB + (lane >> 4) * 16);
    // B (two n-frags via x4): lane l -> row (l>>4)*8 + (l&7), byte ((l>>3)&1)*16
    uint32_t brow = (uint32_t)((lane >> 4) * 8 + (lane & 7));
    uint32_t bbyte = (uint32_t)(((lane >> 3) & 1) * 16);
    uint32_t bO0 = (uint32_t)((warp_n * 32 + 0  + brow) * ARB + bbyte) + ASZ;
    uint32_t bO1 = (uint32_t)((warp_n * 32 + 16 + brow) * ARB + bbyte) + ASZ;

    // ---- prologue: stage tiles 0 and 1; tile 2 into regs ----
    float4 aR[2];
    ldgA(aR, Ag, lda, ctaM, t, 0);
    stsA(sb + 0 * STG, t, aR);
    cpB(sb + 0 * STG + ASZ, Bg, ldb, t, 0);
    cp_commit();
    ldgA(aR, Ag, lda, ctaM, t, BK);
    stsA(sb + 1 * STG, t, aR);
    cpB(sb + 1 * STG + ASZ, Bg, ldb, t, BK);
    cp_commit();
    ldgA(aR, Ag, lda, ctaM, t, 2 * BK);

    // fragment double buffers (k16-level software pipeline)
    uint32_t af[2][2][4];     // [buf][mi][reg]
    uint32_t bf[2][2][4];     // [buf][nhalf][reg]  ([0,1]=n-frag lo, [2,3]=n-frag hi)

    // ---- main loop ----
    for (int kt = 0; kt < nk; kt++) {
        cp_wait<1>();
        __syncthreads();

        uint32_t base = sb + (kt % 3) * STG;
        uint32_t a0 = base + aO0, a1 = base + aO1;
        uint32_t b0 = base + bO0, b1 = base + bO1;

        // prefetch k16=0 fragments; latency hides behind staging issue below
        LDSM4(af[0][0], a0);
        LDSM4(af[0][1], a1);
        LDSM4(bf[0][0], b0);
        LDSM4(bf[0][1], b1);

        // stage tile L = kt + 2
        int L = kt + 2;
        if (L < nk) {
            uint32_t stg = sb + (L % 3) * STG;
            stsA(stg, t, aR);
            if (L + 1 < nk) ldgA(aR, Ag, lda, ctaM, t, (L + 1) * BK);
            cpB(stg + ASZ, Bg, ldb, t, L * BK);
        }
        cp_commit();   // empty group near the tail keeps wait<1> accounting uniform

        // compute: 4 k16 steps, double-buffered fragments, 8 MMAs each
#pragma unroll
        for (int k16 = 0; k16 < 4; k16++) {
            int cur = k16 & 1, nxt = cur ^ 1;
            if (k16 < 3) {
                LDSM4(af[nxt][0], a0 + (k16 + 1) * 32);
                LDSM4(af[nxt][1], a1 + (k16 + 1) * 32);
                LDSM4(bf[nxt][0], b0 + (k16 + 1) * 32);
                LDSM4(bf[nxt][1], b1 + (k16 + 1) * 32);
            }
#pragma unroll
            for (int h = 0; h < 2; h++) {
                mma_f16(acc[0][2 * h],     af[cur][0], bf[cur][h][0], bf[cur][h][1]);
                mma_f16(acc[1][2 * h],     af[cur][1], bf[cur][h][0], bf[cur][h][1]);
                mma_f16(acc[0][2 * h + 1], af[cur][0], bf[cur][h][2], bf[cur][h][3]);
                mma_f16(acc[1][2 * h + 1], af[cur][1], bf[cur][h][2], bf[cur][h][3]);
            }
        }
    }

    // ---- epilogue: optional row scale, store ----
#pragma unroll
    for (int mi = 0; mi < 2; mi++) {
        int r = ctaM + warp_m * 32 + mi * 16 + (lane >> 2);
        float s0 = scale ? scale[r] : 1.0f;
        float s1 = scale ? scale[r + 8] : 1.0f;
#pragma unroll
        for (int ni = 0; ni < 4; ni++) {
            int col = warp_n * 32 + ni * 8 + 2 * (lane & 3);
            float2 v0 = make_float2(acc[mi][ni][0] * s0, acc[mi][ni][1] * s0);
            float2 v1 = make_float2(acc[mi][ni][2] * s1, acc[mi][ni][3] * s1);
            *reinterpret_cast<float2*>(&C[(size_t)r * DIN + col]) = v0;
            *reinterpret_cast<float2*>(&C[(size_t)(r + 8) * DIN + col]) = v1;
        }
    }
}

// ---------------- launch ----------------------------------------------------
extern "C" void kernel_launch(void* const* d_in, const int* in_sizes, int n_in,
                              void* d_out, int out_size) {
    const float* X = (const float*)d_in[0];   // [8192, 256]
    const float* A = (const float*)d_in[1];   // [8192, 8192]
    const float* W = (const float*)d_in[2];   // [256, 256]
    float* out = (float*)d_out;               // [8192, 256]

    cudaFuncSetAttribute(gemm_tc, cudaFuncAttributeMaxDynamicSharedMemorySize, GSMEM);

    rowsum_kernel<<<NROW, 256>>>(A);
    prepYT_kernel<<<dim3(KDIM / 32, DIN / 32), 256>>>(X);
    prepW_kernel<<<(DOUT * DIN / 4) / 256, 256>>>(W);
    gemm_tc<<<NROW / BM, NT, GSMEM>>>(A, nullptr, 0);   // g_H = A_norm @ X
    gemm_tc<<<NROW / BM, NT, GSMEM>>>(nullptr, out, 1); // out = H @ W^T
}